// round 1
// baseline (speedup 1.0000x reference)
#include <cuda_runtime.h>
#include <math.h>
#include <stdint.h>

#define NEMB 20000
#define DEMB 128
#define NA   8192
#define PDIM 10000
#define FEPS 1e-8f

#define BI 64
#define BJ 32

// ---------------- scratch (device globals; no allocation allowed) ----------
__device__ float    g_sims_o[NA];
__device__ float    g_sims_n[NA];
__device__ unsigned g_mkey_o[NEMB];
__device__ unsigned g_mkey_n[NEMB];
__device__ float    g_ssum_o[NEMB];
__device__ float    g_ssum_n[NEMB];
__device__ float    g_cnt[NEMB];
__device__ float    g_dinv[NA];
__device__ float    g_Lu, g_LpNum, g_LpDen, g_Lc;
__device__ int      g_mask_mode;   // 0 = byte(bool), 1 = int32, 2 = float32

// ---------------- helpers ---------------------------------------------------
__device__ __forceinline__ unsigned fkey(float f) {
    unsigned u = __float_as_uint(f);
    return (u & 0x80000000u) ? ~u : (u | 0x80000000u);
}
__device__ __forceinline__ float fkey_inv(unsigned k) {
    return (k & 0x80000000u) ? __uint_as_float(k & 0x7fffffffu)
                             : __uint_as_float(~k);
}

// 4 mask values for elements [idx4*4, idx4*4+4)
__device__ __forceinline__ float4 mask4(const void* m, int mode, int idx4) {
    float4 r;
    if (mode == 0) {                       // packed bytes (bool)
        unsigned w = ((const unsigned*)m)[idx4];
        r.x = (w & 0x000000ffu) ? 1.f : 0.f;
        r.y = (w & 0x0000ff00u) ? 1.f : 0.f;
        r.z = (w & 0x00ff0000u) ? 1.f : 0.f;
        r.w = (w & 0xff000000u) ? 1.f : 0.f;
    } else if (mode == 1) {                // int32 0/1
        int4 v = ((const int4*)m)[idx4];
        r.x = v.x ? 1.f : 0.f; r.y = v.y ? 1.f : 0.f;
        r.z = v.z ? 1.f : 0.f; r.w = v.w ? 1.f : 0.f;
    } else {                               // float32 0.0/1.0
        r = ((const float4*)m)[idx4];
    }
    return r;
}

__device__ __forceinline__ unsigned long long pack2(float x) {
    unsigned long long r;
    asm("mov.b64 %0, {%1, %1};" : "=l"(r) : "f"(x));
    return r;
}
__device__ __forceinline__ void unpack2(unsigned long long v, float& lo, float& hi) {
    asm("mov.b64 {%0, %1}, %2;" : "=f"(lo), "=f"(hi) : "l"(v));
}
__device__ __forceinline__ void ffma2(unsigned long long& d,
                                      unsigned long long a, unsigned long long b) {
    asm("fma.rn.f32x2 %0, %1, %2, %0;" : "+l"(d) : "l"(a), "l"(b));
}

__device__ __forceinline__ float softplusf(float x) {   // log(1+e^x), stable
    return fmaxf(x, 0.f) + log1pf(expf(-fabsf(x)));
}

// ---------------- mask dtype detection (1 warp) -----------------------------
__global__ void detect_mask_kernel(const unsigned* __restrict__ m) {
    int vi = 0, vf = 0, vb = 0;
    for (int i = threadIdx.x; i < 256; i += 32) {
        unsigned w = m[i];
        if (w == 1u) vi++;
        else if (w == 0x3f800000u) vf++;
        else if (w != 0u) vb++;            // e.g. 0x01010101 byte patterns
    }
#pragma unroll
    for (int o = 16; o; o >>= 1) {
        vi += __shfl_xor_sync(~0u, vi, o);
        vf += __shfl_xor_sync(~0u, vf, o);
        vb += __shfl_xor_sync(~0u, vb, o);
    }
    if (threadIdx.x == 0) {
        int mode;
        if (vb >= vi && vb >= vf) mode = 0;
        else if (vi >= vf)        mode = 1;
        else                      mode = 2;
        g_mask_mode = mode;
    }
}

// ---------------- init ------------------------------------------------------
__global__ void init_kernel() {
    int i = blockIdx.x * blockDim.x + threadIdx.x;
    if (i < NEMB) {
        g_mkey_o[i] = 0u; g_mkey_n[i] = 0u;
        g_ssum_o[i] = 0.f; g_ssum_n[i] = 0.f;
        g_cnt[i] = 0.f;
    }
    if (i == 0) { g_Lu = 0.f; g_LpNum = 0.f; g_LpDen = 0.f; g_Lc = 0.f; }
}

// ---------------- L_u -------------------------------------------------------
__global__ void lu_kernel(const float* __restrict__ pred,
                          const int* __restrict__ edges, int nE) {
    int e = blockIdx.x * blockDim.x + threadIdx.x;
    if (e >= nE) return;
    int u = edges[2 * e], v = edges[2 * e + 1];
    float s = __ldg(&pred[(long long)u * PDIM + v]);
    atomicAdd(&g_Lu, softplusf(s));      // -log_sigmoid(-s) = softplus(s)
}

// ---------------- L_p: sims + segment max (warp per edge) -------------------
__global__ void sims_kernel(const float* __restrict__ embO,
                            const float* __restrict__ embN,
                            const int* __restrict__ edges, int nE) {
    int warp = (blockIdx.x * blockDim.x + threadIdx.x) >> 5;
    int lane = threadIdx.x & 31;
    if (warp >= nE) return;
    int u = edges[2 * warp], v = edges[2 * warp + 1];
    const float4* uo = (const float4*)(embO + (long long)u * DEMB);
    const float4* vo = (const float4*)(embO + (long long)v * DEMB);
    const float4* un = (const float4*)(embN + (long long)u * DEMB);
    const float4* vn = (const float4*)(embN + (long long)v * DEMB);
    float4 a = uo[lane], b = vo[lane];
    float4 c = un[lane], d4 = vn[lane];
    float so = a.x * b.x + a.y * b.y + a.z * b.z + a.w * b.w;
    float sn = c.x * d4.x + c.y * d4.y + c.z * d4.z + c.w * d4.w;
#pragma unroll
    for (int o = 16; o; o >>= 1) {
        so += __shfl_xor_sync(~0u, so, o);
        sn += __shfl_xor_sync(~0u, sn, o);
    }
    if (lane == 0) {                         // TAU = 1
        g_sims_o[warp] = so;
        g_sims_n[warp] = sn;
        atomicMax(&g_mkey_o[u], fkey(so));
        atomicMax(&g_mkey_n[u], fkey(sn));
    }
}

// ---------------- L_p: segment exp-sum + counts -----------------------------
__global__ void segsum_kernel(const int* __restrict__ edges, int nE) {
    int e = blockIdx.x * blockDim.x + threadIdx.x;
    if (e >= nE) return;
    int u = edges[2 * e];
    float mo = fkey_inv(g_mkey_o[u]);
    float mn = fkey_inv(g_mkey_n[u]);
    atomicAdd(&g_ssum_o[u], expf(g_sims_o[e] - mo));
    atomicAdd(&g_ssum_n[u], expf(g_sims_n[e] - mn));
    atomicAdd(&g_cnt[u], 1.f);
}

// ---------------- L_p: per-edge logp diff -----------------------------------
__global__ void lp_kernel(const int* __restrict__ edges, int nE) {
    int e = blockIdx.x * blockDim.x + threadIdx.x;
    if (e >= nE) return;
    int u = edges[2 * e];
    if (g_cnt[u] <= 1.f) return;             // mask = counts > 1
    float mo = fkey_inv(g_mkey_o[u]);
    float lseo = logf(g_ssum_o[u] + 1e-30f) + mo;
    float lpo  = logf(expf(g_sims_o[e] - lseo) + FEPS);
    float mn = fkey_inv(g_mkey_n[u]);
    float lsen = logf(g_ssum_n[u] + 1e-30f) + mn;
    float lpn  = logf(expf(g_sims_n[e] - lsen) + FEPS);
    float d = lpn - lpo;
    atomicAdd(&g_LpNum, d * d);
    atomicAdd(&g_LpDen, 1.f);
}

// ---------------- deg / dinv (block per row) --------------------------------
__global__ void deg_kernel(const float4* __restrict__ A4,
                           const void* __restrict__ mask) {
    int row = blockIdx.x;
    int mode = g_mask_mode;
    int base4 = row * (NA / 4);
    float s = 0.f;
    for (int c = threadIdx.x; c < NA / 4; c += blockDim.x) {
        float4 a = A4[base4 + c];
        float4 m = mask4(mask, mode, base4 + c);
        s += a.x * m.x + a.y * m.y + a.z * m.z + a.w * m.w;
    }
    __shared__ float red[8];
#pragma unroll
    for (int o = 16; o; o >>= 1) s += __shfl_xor_sync(~0u, s, o);
    if ((threadIdx.x & 31) == 0) red[threadIdx.x >> 5] = s;
    __syncthreads();
    if (threadIdx.x < 8) {
        float v = red[threadIdx.x];
#pragma unroll
        for (int o = 4; o; o >>= 1) v += __shfl_xor_sync(0xffu, v, o);
        if (threadIdx.x == 0) g_dinv[row] = rsqrtf(v + FEPS);
    }
}

// ---------------- main: fused masked-scaled GEMM + cos epilogue -------------
// Block: 64 output rows x 128 cols, 256 threads, BJ=32 k-tile,
// register-prefetch double buffering, FFMA2 (f32x2) inner product.
__global__ __launch_bounds__(256)
void gemm_kernel(const float* __restrict__ A,
                 const void* __restrict__ mask,
                 const float* __restrict__ H) {
    __shared__ float As[BI][BJ + 1];     // A*mask
    __shared__ float Hs[BJ][DEMB];       // dinv_j * H

    const int tid  = threadIdx.x;
    const int mode = g_mask_mode;
    const int bi   = blockIdx.x * BI;

    // A-tile load mapping: 8 contiguous floats per thread
    const int arow = tid >> 2;            // 0..63
    const int acol = (tid & 3) * 8;       // 0,8,16,24
    // H-tile load mapping: 16 contiguous floats per thread
    const int hrow = tid >> 3;            // 0..31
    const int hcol = (tid & 7) * 16;      // 0..112
    // compute mapping: thread owns 2 rows x 16 cols
    const int cg = tid & 7;
    const int rg = tid >> 3;
    const int r0 = rg * 2;
    const int r1 = r0 + 1;
    const int c0 = cg * 16;

    unsigned long long acc[2][8];
#pragma unroll
    for (int r = 0; r < 2; r++)
#pragma unroll
        for (int k = 0; k < 8; k++) acc[r][k] = 0ull;

    // prefetch registers
    float4 pa0, pa1, pm0, pm1, ph[4];
    float  pdv;

    auto loadTile = [&](int jt) {
        long long abase = (long long)(bi + arow) * NA + jt + acol;
        pa0 = *(const float4*)(A + abase);
        pa1 = *(const float4*)(A + abase + 4);
        int i4 = (int)(abase >> 2);
        pm0 = mask4(mask, mode, i4);
        pm1 = mask4(mask, mode, i4 + 1);
        pdv = g_dinv[jt + hrow];
        const float4* hb = (const float4*)(H + (long long)(jt + hrow) * DEMB + hcol);
#pragma unroll
        for (int q = 0; q < 4; q++) ph[q] = hb[q];
    };

    loadTile(0);
    for (int jt = 0; jt < NA; jt += BJ) {
        __syncthreads();
        // commit prefetched tile to smem
        As[arow][acol + 0] = pa0.x * pm0.x;
        As[arow][acol + 1] = pa0.y * pm0.y;
        As[arow][acol + 2] = pa0.z * pm0.z;
        As[arow][acol + 3] = pa0.w * pm0.w;
        As[arow][acol + 4] = pa1.x * pm1.x;
        As[arow][acol + 5] = pa1.y * pm1.y;
        As[arow][acol + 6] = pa1.z * pm1.z;
        As[arow][acol + 7] = pa1.w * pm1.w;
        float dv = pdv;
#pragma unroll
        for (int q = 0; q < 4; q++) {
            *(float4*)&Hs[hrow][hcol + q * 4] =
                make_float4(ph[q].x * dv, ph[q].y * dv, ph[q].z * dv, ph[q].w * dv);
        }
        __syncthreads();
        if (jt + BJ < NA) loadTile(jt + BJ);   // overlap next-tile loads with compute

#pragma unroll
        for (int j = 0; j < BJ; j++) {
            unsigned long long a0 = pack2(As[r0][j]);
            unsigned long long a1 = pack2(As[r1][j]);
            const ulonglong2* hp = (const ulonglong2*)&Hs[j][c0];
#pragma unroll
            for (int k = 0; k < 4; k++) {
                ulonglong2 h = hp[k];
                ffma2(acc[0][2 * k], a0, h.x);
                ffma2(acc[0][2 * k + 1], a0, h.y);
                ffma2(acc[1][2 * k], a1, h.x);
                ffma2(acc[1][2 * k + 1], a1, h.y);
            }
        }
    }

    // epilogue: cos similarity + softplus per row
#pragma unroll
    for (int r = 0; r < 2; r++) {
        int gi = bi + r0 + r;
        float num = 0.f, sq = 0.f, hsq = 0.f;
        const float4* hb = (const float4*)(H + (long long)gi * DEMB + c0);
#pragma unroll
        for (int k = 0; k < 4; k++) {
            float4 h = hb[k];
            float lo, hi;
            unpack2(acc[r][2 * k], lo, hi);
            num += h.x * lo + h.y * hi;
            sq  += lo * lo + hi * hi;
            unpack2(acc[r][2 * k + 1], lo, hi);
            num += h.z * lo + h.w * hi;
            sq  += lo * lo + hi * hi;
            hsq += h.x * h.x + h.y * h.y + h.z * h.z + h.w * h.w;
        }
#pragma unroll
        for (int o = 4; o; o >>= 1) {        // reduce across the 8 col-group lanes
            num += __shfl_xor_sync(~0u, num, o);
            sq  += __shfl_xor_sync(~0u, sq, o);
            hsq += __shfl_xor_sync(~0u, hsq, o);
        }
        if (cg == 0) {
            float dv   = g_dinv[gi];          // H_p = dv * acc
            float den  = fmaxf(sqrtf(hsq) * (dv * sqrtf(sq)), FEPS);
            float cosv = (dv * num) / den;
            atomicAdd(&g_Lc, softplusf(-cosv));   // -log_sigmoid(cos)
        }
    }
}

// ---------------- finalize --------------------------------------------------
__global__ void final_kernel(float* __restrict__ out, int nU) {
    float L_u = g_Lu / (float)nU;
    float L_p = g_LpNum / fmaxf(g_LpDen, 1.f);
    float L_c = g_Lc / (float)NA;
    out[0] = L_u + L_p + 0.01f * L_c;
    out[1] = L_u;
    out[2] = L_p;
    out[3] = L_c;
}

// ---------------- launch ----------------------------------------------------
extern "C" void kernel_launch(void* const* d_in, const int* in_sizes, int n_in,
                              void* d_out, int out_size) {
    const float* pred = (const float*)d_in[0];
    const float* embO = (const float*)d_in[1];
    const float* embN = (const float*)d_in[2];
    const float* A    = (const float*)d_in[3];
    const float* H    = (const float*)d_in[4];
    const int*   uE   = (const int*)d_in[5];
    const int*   rE   = (const int*)d_in[6];
    const void*  mask = d_in[7];
    int nU = in_sizes[5] / 2;
    int nR = in_sizes[6] / 2;

    detect_mask_kernel<<<1, 32>>>((const unsigned*)mask);
    init_kernel<<<(NEMB + 255) / 256, 256>>>();
    lu_kernel<<<(nU + 255) / 256, 256>>>(pred, uE, nU);
    sims_kernel<<<(nR * 32 + 255) / 256, 256>>>(embO, embN, rE, nR);
    segsum_kernel<<<(nR + 255) / 256, 256>>>(rE, nR);
    lp_kernel<<<(nR + 255) / 256, 256>>>(rE, nR);
    deg_kernel<<<NA, 256>>>((const float4*)A, mask);
    gemm_kernel<<<NA / BI, 256>>>(A, mask, H);
    final_kernel<<<1, 1>>>((float*)d_out, nU);
}

// round 3
// speedup vs baseline: 11.1993x; 11.1993x over previous
#include <cuda_runtime.h>
#include <cuda_bf16.h>
#include <math.h>
#include <stdint.h>

#define NEMB 20000
#define DEMB 128
#define NA   8192
#define PDIM 10000
#define FEPS 1e-8f

// ---------------- scratch (device globals; no allocation allowed) ----------
__device__ float    g_sims_o[NA];
__device__ float    g_sims_n[NA];
__device__ unsigned g_mkey_o[NEMB];
__device__ unsigned g_mkey_n[NEMB];
__device__ float    g_ssum_o[NEMB];
__device__ float    g_ssum_n[NEMB];
__device__ float    g_cnt[NEMB];
__device__ float    g_dinv[NA];
__device__ float    g_Lu, g_LpNum, g_LpDen, g_Lc;
__device__ int      g_mask_mode;   // 0 = byte(bool), 1 = int32, 2 = float32

// big scratch: W = bf16(A * mask) (128 MB), Hs = bf16(dinv_j * H[j][:]) (2 MB)
__device__ unsigned short g_Wbf[(size_t)NA * NA];
__device__ unsigned short g_Hs[(size_t)NA * DEMB];

// ---------------- helpers ---------------------------------------------------
__device__ __forceinline__ unsigned fkey(float f) {
    unsigned u = __float_as_uint(f);
    return (u & 0x80000000u) ? ~u : (u | 0x80000000u);
}
__device__ __forceinline__ float fkey_inv(unsigned k) {
    return (k & 0x80000000u) ? __uint_as_float(k & 0x7fffffffu)
                             : __uint_as_float(~k);
}
__device__ __forceinline__ float4 mask4(const void* m, int mode, int idx4) {
    float4 r;
    if (mode == 0) {                       // packed bytes (bool)
        unsigned w = ((const unsigned*)m)[idx4];
        r.x = (w & 0x000000ffu) ? 1.f : 0.f;
        r.y = (w & 0x0000ff00u) ? 1.f : 0.f;
        r.z = (w & 0x00ff0000u) ? 1.f : 0.f;
        r.w = (w & 0xff000000u) ? 1.f : 0.f;
    } else if (mode == 1) {                // int32 0/1
        int4 v = ((const int4*)m)[idx4];
        r.x = v.x ? 1.f : 0.f; r.y = v.y ? 1.f : 0.f;
        r.z = v.z ? 1.f : 0.f; r.w = v.w ? 1.f : 0.f;
    } else {                               // float32
        r = ((const float4*)m)[idx4];
    }
    return r;
}
__device__ __forceinline__ float softplusf(float x) {
    return fmaxf(x, 0.f) + log1pf(expf(-fabsf(x)));
}
__device__ __forceinline__ uint32_t s2u(const void* p) {
    uint32_t a;
    asm("{ .reg .u64 t; cvta.to.shared.u64 t, %1; cvt.u32.u64 %0, t; }"
        : "=r"(a) : "l"(p));
    return a;
}
__device__ __forceinline__ void cp16(uint32_t dst, const void* src) {
    asm volatile("cp.async.cg.shared.global [%0], [%1], 16;\n"
                 :: "r"(dst), "l"(src) : "memory");
}
#define CP_COMMIT() asm volatile("cp.async.commit_group;" ::: "memory")
#define CP_WAIT2()  asm volatile("cp.async.wait_group 2;" ::: "memory")

__device__ __forceinline__ void ldsm4(uint32_t* r, uint32_t addr) {
    asm volatile("ldmatrix.sync.aligned.m8n8.x4.shared.b16 {%0,%1,%2,%3}, [%4];"
                 : "=r"(r[0]), "=r"(r[1]), "=r"(r[2]), "=r"(r[3]) : "r"(addr));
}
__device__ __forceinline__ void ldsm4t(uint32_t* r, uint32_t addr) {
    asm volatile("ldmatrix.sync.aligned.m8n8.x4.trans.shared.b16 {%0,%1,%2,%3}, [%4];"
                 : "=r"(r[0]), "=r"(r[1]), "=r"(r[2]), "=r"(r[3]) : "r"(addr));
}
__device__ __forceinline__ void mma16816(float* c, const uint32_t* a, const uint32_t* b) {
    asm volatile(
        "mma.sync.aligned.m16n8k16.row.col.f32.bf16.bf16.f32 "
        "{%0,%1,%2,%3}, {%4,%5,%6,%7}, {%8,%9}, {%0,%1,%2,%3};"
        : "+f"(c[0]), "+f"(c[1]), "+f"(c[2]), "+f"(c[3])
        : "r"(a[0]), "r"(a[1]), "r"(a[2]), "r"(a[3]), "r"(b[0]), "r"(b[1]));
}

// ---------------- mask dtype detection --------------------------------------
__global__ void detect_mask_kernel(const unsigned* __restrict__ m) {
    int vi = 0, vf = 0, vb = 0;
    for (int i = threadIdx.x; i < 256; i += 32) {
        unsigned w = m[i];
        if (w == 1u) vi++;
        else if (w == 0x3f800000u) vf++;
        else if (w != 0u) vb++;
    }
#pragma unroll
    for (int o = 16; o; o >>= 1) {
        vi += __shfl_xor_sync(~0u, vi, o);
        vf += __shfl_xor_sync(~0u, vf, o);
        vb += __shfl_xor_sync(~0u, vb, o);
    }
    if (threadIdx.x == 0) {
        int mode;
        if (vb >= vi && vb >= vf) mode = 0;
        else if (vi >= vf)        mode = 1;
        else                      mode = 2;
        g_mask_mode = mode;
    }
}

// ---------------- init ------------------------------------------------------
__global__ void init_kernel() {
    int i = blockIdx.x * blockDim.x + threadIdx.x;
    if (i < NEMB) {
        g_mkey_o[i] = 0u; g_mkey_n[i] = 0u;
        g_ssum_o[i] = 0.f; g_ssum_n[i] = 0.f;
        g_cnt[i] = 0.f;
    }
    if (i == 0) { g_Lu = 0.f; g_LpNum = 0.f; g_LpDen = 0.f; g_Lc = 0.f; }
}

// ---------------- L_u -------------------------------------------------------
__global__ void lu_kernel(const float* __restrict__ pred,
                          const int* __restrict__ edges, int nE) {
    int e = blockIdx.x * blockDim.x + threadIdx.x;
    if (e >= nE) return;
    int u = edges[2 * e], v = edges[2 * e + 1];
    float s = __ldg(&pred[(long long)u * PDIM + v]);
    atomicAdd(&g_Lu, softplusf(s));
}

// ---------------- L_p chain -------------------------------------------------
__global__ void sims_kernel(const float* __restrict__ embO,
                            const float* __restrict__ embN,
                            const int* __restrict__ edges, int nE) {
    int warp = (blockIdx.x * blockDim.x + threadIdx.x) >> 5;
    int lane = threadIdx.x & 31;
    if (warp >= nE) return;
    int u = edges[2 * warp], v = edges[2 * warp + 1];
    const float4* uo = (const float4*)(embO + (long long)u * DEMB);
    const float4* vo = (const float4*)(embO + (long long)v * DEMB);
    const float4* un = (const float4*)(embN + (long long)u * DEMB);
    const float4* vn = (const float4*)(embN + (long long)v * DEMB);
    float4 a = uo[lane], b = vo[lane];
    float4 c = un[lane], d4 = vn[lane];
    float so = a.x * b.x + a.y * b.y + a.z * b.z + a.w * b.w;
    float sn = c.x * d4.x + c.y * d4.y + c.z * d4.z + c.w * d4.w;
#pragma unroll
    for (int o = 16; o; o >>= 1) {
        so += __shfl_xor_sync(~0u, so, o);
        sn += __shfl_xor_sync(~0u, sn, o);
    }
    if (lane == 0) {
        g_sims_o[warp] = so;
        g_sims_n[warp] = sn;
        atomicMax(&g_mkey_o[u], fkey(so));
        atomicMax(&g_mkey_n[u], fkey(sn));
    }
}

__global__ void segsum_kernel(const int* __restrict__ edges, int nE) {
    int e = blockIdx.x * blockDim.x + threadIdx.x;
    if (e >= nE) return;
    int u = edges[2 * e];
    float mo = fkey_inv(g_mkey_o[u]);
    float mn = fkey_inv(g_mkey_n[u]);
    atomicAdd(&g_ssum_o[u], expf(g_sims_o[e] - mo));
    atomicAdd(&g_ssum_n[u], expf(g_sims_n[e] - mn));
    atomicAdd(&g_cnt[u], 1.f);
}

__global__ void lp_kernel(const int* __restrict__ edges, int nE) {
    int e = blockIdx.x * blockDim.x + threadIdx.x;
    if (e >= nE) return;
    int u = edges[2 * e];
    if (g_cnt[u] <= 1.f) return;
    float mo = fkey_inv(g_mkey_o[u]);
    float lseo = logf(g_ssum_o[u] + 1e-30f) + mo;
    float lpo  = logf(expf(g_sims_o[e] - lseo) + FEPS);
    float mn = fkey_inv(g_mkey_n[u]);
    float lsen = logf(g_ssum_n[u] + 1e-30f) + mn;
    float lpn  = logf(expf(g_sims_n[e] - lsen) + FEPS);
    float d = lpn - lpo;
    atomicAdd(&g_LpNum, d * d);
    atomicAdd(&g_LpDen, 1.f);
}

// ---------------- deg + bf16 convert (one pass over A) ----------------------
__global__ __launch_bounds__(256)
void deg_cvt_kernel(const float4* __restrict__ A4, const void* __restrict__ mask) {
    int row = blockIdx.x;
    int mode = g_mask_mode;
    int base4 = row * (NA / 4);
    uint2* __restrict__ W2 = (uint2*)g_Wbf;   // 4 bf16 per uint2
    float s = 0.f;
    for (int c = threadIdx.x; c < NA / 4; c += 256) {
        float4 a = A4[base4 + c];
        float4 m = mask4(mask, mode, base4 + c);
        float x0 = a.x * m.x, x1 = a.y * m.y, x2 = a.z * m.z, x3 = a.w * m.w;
        s += (x0 + x1) + (x2 + x3);
        __nv_bfloat162 p0 = __floats2bfloat162_rn(x0, x1);
        __nv_bfloat162 p1 = __floats2bfloat162_rn(x2, x3);
        uint2 o;
        o.x = *(unsigned*)&p0;
        o.y = *(unsigned*)&p1;
        W2[base4 + c] = o;
    }
    __shared__ float red[8];
#pragma unroll
    for (int o = 16; o; o >>= 1) s += __shfl_xor_sync(~0u, s, o);
    if ((threadIdx.x & 31) == 0) red[threadIdx.x >> 5] = s;
    __syncthreads();
    if (threadIdx.x < 8) {
        float v = red[threadIdx.x];
#pragma unroll
        for (int o = 4; o; o >>= 1) v += __shfl_xor_sync(0xffu, v, o);
        if (threadIdx.x == 0) g_dinv[row] = rsqrtf(v + FEPS);
    }
}

// ---------------- Hs = bf16(dinv_j * H[j][:]), row-major --------------------
__global__ __launch_bounds__(256)
void hscale_kernel(const float4* __restrict__ H4) {
    int i = blockIdx.x * 256 + threadIdx.x;      // one float4 (4 elems)
    if (i >= NA * DEMB / 4) return;
    int j = i >> 5;                              // 32 float4 per row
    float dv = g_dinv[j];
    float4 h = H4[i];
    __nv_bfloat162 p0 = __floats2bfloat162_rn(h.x * dv, h.y * dv);
    __nv_bfloat162 p1 = __floats2bfloat162_rn(h.z * dv, h.w * dv);
    uint2 o;
    o.x = *(unsigned*)&p0;
    o.y = *(unsigned*)&p1;
    ((uint2*)g_Hs)[i] = o;
}

// ---------------- mma.sync GEMM + fused cos epilogue ------------------------
// Block: M=64 x N=128, K-tile 32, 8 warps (2 M x 4 N), warp tile 32x32.
// 4-stage cp.async pipeline. A = W[64][32] bf16 (swizzled), B = Hs[32][128].
#define MBLK   64
#define KBLK   32
#define STAGES 4
#define NCHUNK (NA / KBLK)              // 256
#define ATILE  4096                     // 64*32*2
#define BTILE  8192                     // 32*128*2
#define STAGEB (ATILE + BTILE)          // 12288
#define GEMM_SMEM (STAGES * STAGEB)     // 49152

__global__ __launch_bounds__(256, 1)
void gemm_mma_kernel(const float* __restrict__ H) {
    extern __shared__ char smem[];
    __shared__ float s_num[MBLK], s_sq[MBLK];
    uint32_t sb = s2u(smem);
    const int tid = threadIdx.x;
    const int lane = tid & 31;
    const int wid = tid >> 5;
    const int wm = wid & 1;              // 0..1 (M)
    const int wn = wid >> 1;             // 0..3 (N)
    const int bi = blockIdx.x * MBLK;

    if (tid < MBLK) { s_num[tid] = 0.f; s_sq[tid] = 0.f; }

    const unsigned short* __restrict__ W = g_Wbf;
    const unsigned short* __restrict__ Hs = g_Hs;

    // load mappings
    const int a_r = tid >> 2;            // 0..63
    const int a_c = tid & 3;             // 16B chunk 0..3
    const uint32_t a_off = (uint32_t)(a_r * 64 + ((a_c ^ (a_r & 3)) << 4));
    const long long a_src = (long long)(bi + a_r) * NA + a_c * 8;

    auto issue_loads = [&](int n) {
        uint32_t st = sb + (n % STAGES) * STAGEB;
        long long j0 = (long long)n * KBLK;
        cp16(st + a_off, W + a_src + j0);
#pragma unroll
        for (int q = 0; q < 2; q++) {
            int id = tid + q * 256;
            int k = id >> 4;             // 0..31
            int c = id & 15;             // 0..15
            uint32_t off = (uint32_t)(k * 256 + ((c ^ (k & 7)) << 4));
            cp16(st + ATILE + off, Hs + (j0 + k) * DEMB + c * 8);
        }
        CP_COMMIT();
    };

    float acc[2][4][4];
#pragma unroll
    for (int mt = 0; mt < 2; mt++)
#pragma unroll
        for (int nt = 0; nt < 4; nt++)
#pragma unroll
            for (int q = 0; q < 4; q++) acc[mt][nt][q] = 0.f;

    // ldmatrix address components (constant per thread)
    const int grp = lane >> 3;                 // 0..3
    const int l7  = lane & 7;
    // A: groups: g0 rows+0..7 chunk+0 | g1 rows+8..15 chunk+0 | g2 rows 0..7 chunk+1 | g3 rows+8 chunk+1
    const int ar_base = wm * 32 + l7 + ((grp & 1) << 3);
    const int ac_add  = grp >> 1;
    // B (.trans): g0 k+0..7 cn+0 | g1 k+8..15 cn+0 | g2 k0..7 cn+1 | g3 k+8 cn+1
    const int bk_base = l7 + ((grp & 1) << 3);
    const int bc_add  = grp >> 1;

    issue_loads(0); issue_loads(1); issue_loads(2);

    for (int c = 0; c < NCHUNK; c++) {
        CP_WAIT2();
        __syncthreads();
        uint32_t Ab = sb + (c % STAGES) * STAGEB;
        uint32_t Bb = Ab + ATILE;

#pragma unroll
        for (int kk = 0; kk < 2; kk++) {       // two k16 steps
            uint32_t af[2][4];
#pragma unroll
            for (int mt = 0; mt < 2; mt++) {
                int r = ar_base + mt * 16;
                int ch = kk * 2 + ac_add;
                ldsm4(af[mt], Ab + (uint32_t)(r * 64 + ((ch ^ (r & 3)) << 4)));
            }
            uint32_t bf[4][2];
#pragma unroll
            for (int cp = 0; cp < 2; cp++) {
                int k = kk * 16 + bk_base;
                int cn = wn * 4 + cp * 2 + bc_add;
                uint32_t t4[4];
                ldsm4t(t4, Bb + (uint32_t)(k * 256 + ((cn ^ (k & 7)) << 4)));
                bf[cp * 2 + 0][0] = t4[0]; bf[cp * 2 + 0][1] = t4[1];
                bf[cp * 2 + 1][0] = t4[2]; bf[cp * 2 + 1][1] = t4[3];
            }
#pragma unroll
            for (int mt = 0; mt < 2; mt++)
#pragma unroll
                for (int nt = 0; nt < 4; nt++)
                    mma16816(acc[mt][nt], af[mt], bf[nt]);
        }

        int n = c + 3;
        if (n < NCHUNK) issue_loads(n);
        else            CP_COMMIT();
    }

    // ---- epilogue: per-row num = <H, Hp>, sq = |Hp|^2 ----
    __syncthreads();
#pragma unroll
    for (int mt = 0; mt < 2; mt++) {
#pragma unroll
        for (int half = 0; half < 2; half++) {
            int rl = wm * 32 + mt * 16 + half * 8 + (lane >> 2);
            long long gi = bi + rl;
            float num = 0.f, sq = 0.f;
#pragma unroll
            for (int nt = 0; nt < 4; nt++) {
                int col = wn * 32 + nt * 8 + (lane & 3) * 2;
                float v0 = acc[mt][nt][half * 2 + 0];
                float v1 = acc[mt][nt][half * 2 + 1];
                float h0 = H[gi * DEMB + col];
                float h1 = H[gi * DEMB + col + 1];
                num += h0 * v0 + h1 * v1;
                sq  += v0 * v0 + v1 * v1;
            }
            num += __shfl_xor_sync(~0u, num, 1);
            num += __shfl_xor_sync(~0u, num, 2);
            sq  += __shfl_xor_sync(~0u, sq, 1);
            sq  += __shfl_xor_sync(~0u, sq, 2);
            if ((lane & 3) == 0) {
                atomicAdd(&s_num[rl], num);
                atomicAdd(&s_sq[rl], sq);
            }
        }
    }
    __syncthreads();

    if (tid < MBLK) {
        long long gi = bi + tid;
        const float4* hb = (const float4*)(H + gi * DEMB);
        float hsq = 0.f;
#pragma unroll
        for (int q = 0; q < 32; q++) {
            float4 h = hb[q];
            hsq += h.x * h.x + h.y * h.y + h.z * h.z + h.w * h.w;
        }
        float dv  = g_dinv[gi];
        float den = fmaxf(sqrtf(hsq) * (dv * sqrtf(s_sq[tid])), FEPS);
        float cosv = dv * s_num[tid] / den;
        float val = softplusf(-cosv);
#pragma unroll
        for (int o = 16; o; o >>= 1) val += __shfl_xor_sync(~0u, val, o);
        if ((tid & 31) == 0) atomicAdd(&g_Lc, val);
    }
}

// ---------------- finalize --------------------------------------------------
__global__ void final_kernel(float* __restrict__ out, int nU) {
    float L_u = g_Lu / (float)nU;
    float L_p = g_LpNum / fmaxf(g_LpDen, 1.f);
    float L_c = g_Lc / (float)NA;
    out[0] = L_u + L_p + 0.01f * L_c;
    out[1] = L_u;
    out[2] = L_p;
    out[3] = L_c;
}

// ---------------- launch ----------------------------------------------------
extern "C" void kernel_launch(void* const* d_in, const int* in_sizes, int n_in,
                              void* d_out, int out_size) {
    const float* pred = (const float*)d_in[0];
    const float* embO = (const float*)d_in[1];
    const float* embN = (const float*)d_in[2];
    const float* A    = (const float*)d_in[3];
    const float* H    = (const float*)d_in[4];
    const int*   uE   = (const int*)d_in[5];
    const int*   rE   = (const int*)d_in[6];
    const void*  mask = d_in[7];
    int nU = in_sizes[5] / 2;
    int nR = in_sizes[6] / 2;

    cudaFuncSetAttribute(gemm_mma_kernel,
                         cudaFuncAttributeMaxDynamicSharedMemorySize, GEMM_SMEM);

    detect_mask_kernel<<<1, 32>>>((const unsigned*)mask);
    init_kernel<<<(NEMB + 255) / 256, 256>>>();
    lu_kernel<<<(nU + 255) / 256, 256>>>(pred, uE, nU);
    sims_kernel<<<(nR * 32 + 255) / 256, 256>>>(embO, embN, rE, nR);
    segsum_kernel<<<(nR + 255) / 256, 256>>>(rE, nR);
    lp_kernel<<<(nR + 255) / 256, 256>>>(rE, nR);
    deg_cvt_kernel<<<NA, 256>>>((const float4*)A, mask);
    hscale_kernel<<<(NA * DEMB / 4 + 255) / 256, 256>>>((const float4*)H);
    gemm_mma_kernel<<<NA / MBLK, 256, GEMM_SMEM>>>(H);
    final_kernel<<<1, 1>>>((float*)d_out, nU);
}

// round 4
// speedup vs baseline: 14.1309x; 1.2618x over previous
#include <cuda_runtime.h>
#include <cuda_bf16.h>
#include <math.h>
#include <stdint.h>

#define NEMB 20000
#define DEMB 128
#define NA   8192
#define PDIM 10000
#define FEPS 1e-8f

// ---------------- scratch (device globals; no allocation allowed) ----------
__device__ float    g_sims_o[NA];
__device__ float    g_sims_n[NA];
__device__ unsigned g_mkey_o[NEMB];
__device__ unsigned g_mkey_n[NEMB];
__device__ float    g_ssum_o[NEMB];
__device__ float    g_ssum_n[NEMB];
__device__ float    g_cnt[NEMB];
__device__ float    g_dinv[NA];
__device__ float    g_Lu, g_LpNum, g_LpDen, g_Lc;
__device__ int      g_mask_mode;   // 0 = byte(bool), 1 = int32, 2 = float32

// big scratch: W = bf16(A * mask) (128 MB), Hs = bf16(dinv_j * H[j][:]) (2 MB)
__device__ unsigned short g_Wbf[(size_t)NA * NA];
__device__ unsigned short g_Hs[(size_t)NA * DEMB];

// ---------------- helpers ---------------------------------------------------
__device__ __forceinline__ unsigned fkey(float f) {
    unsigned u = __float_as_uint(f);
    return (u & 0x80000000u) ? ~u : (u | 0x80000000u);
}
__device__ __forceinline__ float fkey_inv(unsigned k) {
    return (k & 0x80000000u) ? __uint_as_float(k & 0x7fffffffu)
                             : __uint_as_float(~k);
}
__device__ __forceinline__ float4 mask4(const void* m, int mode, int idx4) {
    float4 r;
    if (mode == 0) {                       // packed bytes (bool)
        unsigned w = ((const unsigned*)m)[idx4];
        r.x = (w & 0x000000ffu) ? 1.f : 0.f;
        r.y = (w & 0x0000ff00u) ? 1.f : 0.f;
        r.z = (w & 0x00ff0000u) ? 1.f : 0.f;
        r.w = (w & 0xff000000u) ? 1.f : 0.f;
    } else if (mode == 1) {                // int32 0/1
        int4 v = ((const int4*)m)[idx4];
        r.x = v.x ? 1.f : 0.f; r.y = v.y ? 1.f : 0.f;
        r.z = v.z ? 1.f : 0.f; r.w = v.w ? 1.f : 0.f;
    } else {                               // float32
        r = ((const float4*)m)[idx4];
    }
    return r;
}
__device__ __forceinline__ float softplusf(float x) {
    return fmaxf(x, 0.f) + log1pf(expf(-fabsf(x)));
}
__device__ __forceinline__ uint32_t s2u(const void* p) {
    uint32_t a;
    asm("{ .reg .u64 t; cvta.to.shared.u64 t, %1; cvt.u32.u64 %0, t; }"
        : "=r"(a) : "l"(p));
    return a;
}
__device__ __forceinline__ void cp16(uint32_t dst, const void* src) {
    asm volatile("cp.async.cg.shared.global [%0], [%1], 16;\n"
                 :: "r"(dst), "l"(src) : "memory");
}
#define CP_COMMIT() asm volatile("cp.async.commit_group;" ::: "memory")
#define CP_WAIT2()  asm volatile("cp.async.wait_group 2;" ::: "memory")

__device__ __forceinline__ void ldsm4(uint32_t* r, uint32_t addr) {
    asm volatile("ldmatrix.sync.aligned.m8n8.x4.shared.b16 {%0,%1,%2,%3}, [%4];"
                 : "=r"(r[0]), "=r"(r[1]), "=r"(r[2]), "=r"(r[3]) : "r"(addr));
}
__device__ __forceinline__ void ldsm4t(uint32_t* r, uint32_t addr) {
    asm volatile("ldmatrix.sync.aligned.m8n8.x4.trans.shared.b16 {%0,%1,%2,%3}, [%4];"
                 : "=r"(r[0]), "=r"(r[1]), "=r"(r[2]), "=r"(r[3]) : "r"(addr));
}
__device__ __forceinline__ void mma16816(float* c, const uint32_t* a, const uint32_t* b) {
    asm volatile(
        "mma.sync.aligned.m16n8k16.row.col.f32.bf16.bf16.f32 "
        "{%0,%1,%2,%3}, {%4,%5,%6,%7}, {%8,%9}, {%0,%1,%2,%3};"
        : "+f"(c[0]), "+f"(c[1]), "+f"(c[2]), "+f"(c[3])
        : "r"(a[0]), "r"(a[1]), "r"(a[2]), "r"(a[3]), "r"(b[0]), "r"(b[1]));
}

// ---------------- K1: init + mask dtype detection ---------------------------
__global__ void init_kernel(const unsigned* __restrict__ m) {
    int i = blockIdx.x * blockDim.x + threadIdx.x;
    if (i < NEMB) {
        g_mkey_o[i] = 0u; g_mkey_n[i] = 0u;
        g_ssum_o[i] = 0.f; g_ssum_n[i] = 0.f;
        g_cnt[i] = 0.f;
    }
    if (i == 0) { g_Lu = 0.f; g_LpNum = 0.f; g_LpDen = 0.f; g_Lc = 0.f; }
    if (blockIdx.x == 0 && threadIdx.x < 32) {     // warp 0 detects mask dtype
        int vi = 0, vf = 0, vb = 0;
        for (int k = threadIdx.x; k < 256; k += 32) {
            unsigned w = m[k];
            if (w == 1u) vi++;
            else if (w == 0x3f800000u) vf++;
            else if (w != 0u) vb++;
        }
#pragma unroll
        for (int o = 16; o; o >>= 1) {
            vi += __shfl_xor_sync(~0u, vi, o);
            vf += __shfl_xor_sync(~0u, vf, o);
            vb += __shfl_xor_sync(~0u, vb, o);
        }
        if (threadIdx.x == 0) {
            int mode;
            if (vb >= vi && vb >= vf) mode = 0;
            else if (vi >= vf)        mode = 1;
            else                      mode = 2;
            g_mask_mode = mode;
        }
    }
}

// ---------------- K2 pieces -------------------------------------------------
__device__ __forceinline__ void deg_cvt_block(int row, const float4* __restrict__ A4,
                                              const void* __restrict__ mask) {
    int mode = g_mask_mode;
    int base4 = row * (NA / 4);
    uint2* __restrict__ W2 = (uint2*)g_Wbf;
    float s = 0.f;
    for (int c = threadIdx.x; c < NA / 4; c += 256) {
        float4 a = A4[base4 + c];
        float4 m = mask4(mask, mode, base4 + c);
        float x0 = a.x * m.x, x1 = a.y * m.y, x2 = a.z * m.z, x3 = a.w * m.w;
        s += (x0 + x1) + (x2 + x3);
        __nv_bfloat162 p0 = __floats2bfloat162_rn(x0, x1);
        __nv_bfloat162 p1 = __floats2bfloat162_rn(x2, x3);
        uint2 o;
        o.x = *(unsigned*)&p0;
        o.y = *(unsigned*)&p1;
        W2[base4 + c] = o;
    }
    __shared__ float red[8];
#pragma unroll
    for (int o = 16; o; o >>= 1) s += __shfl_xor_sync(~0u, s, o);
    if ((threadIdx.x & 31) == 0) red[threadIdx.x >> 5] = s;
    __syncthreads();
    if (threadIdx.x < 8) {
        float v = red[threadIdx.x];
#pragma unroll
        for (int o = 4; o; o >>= 1) v += __shfl_xor_sync(0xffu, v, o);
        if (threadIdx.x == 0) g_dinv[row] = rsqrtf(v + FEPS);
    }
}

__device__ __forceinline__ void lu_block(int blk, const float* __restrict__ pred,
                                         const int* __restrict__ edges, int nE) {
    int e = blk * 256 + threadIdx.x;
    if (e >= nE) return;
    int u = edges[2 * e], v = edges[2 * e + 1];
    float s = __ldg(&pred[(long long)u * PDIM + v]);
    atomicAdd(&g_Lu, softplusf(s));
}

__device__ __forceinline__ void sims_block(int blk, const float* __restrict__ embO,
                                           const float* __restrict__ embN,
                                           const int* __restrict__ edges, int nE) {
    int warp = (blk * 256 + threadIdx.x) >> 5;
    int lane = threadIdx.x & 31;
    if (warp >= nE) return;
    int u = edges[2 * warp], v = edges[2 * warp + 1];
    const float4* uo = (const float4*)(embO + (long long)u * DEMB);
    const float4* vo = (const float4*)(embO + (long long)v * DEMB);
    const float4* un = (const float4*)(embN + (long long)u * DEMB);
    const float4* vn = (const float4*)(embN + (long long)v * DEMB);
    float4 a = uo[lane], b = vo[lane];
    float4 c = un[lane], d4 = vn[lane];
    float so = a.x * b.x + a.y * b.y + a.z * b.z + a.w * b.w;
    float sn = c.x * d4.x + c.y * d4.y + c.z * d4.z + c.w * d4.w;
#pragma unroll
    for (int o = 16; o; o >>= 1) {
        so += __shfl_xor_sync(~0u, so, o);
        sn += __shfl_xor_sync(~0u, sn, o);
    }
    if (lane == 0) {
        g_sims_o[warp] = so;
        g_sims_n[warp] = sn;
        atomicMax(&g_mkey_o[u], fkey(so));
        atomicMax(&g_mkey_n[u], fkey(sn));
    }
}

// K2: blocks [0,8192) deg rows | [8192,8208) lu | [8208,9232) sims
__global__ __launch_bounds__(256)
void mega1_kernel(const float4* __restrict__ A4, const void* __restrict__ mask,
                  const float* __restrict__ pred,
                  const float* __restrict__ embO, const float* __restrict__ embN,
                  const int* __restrict__ uE, int nU,
                  const int* __restrict__ rE, int nR) {
    int b = blockIdx.x;
    if (b < NA)            deg_cvt_block(b, A4, mask);
    else if (b < NA + 16)  lu_block(b - NA, pred, uE, nU);
    else                   sims_block(b - NA - 16, embO, embN, rE, nR);
}

// ---------------- K3: segsum + hscale ---------------------------------------
__device__ __forceinline__ void segsum_block(int blk, const int* __restrict__ edges, int nE) {
    int e = blk * 256 + threadIdx.x;
    if (e >= nE) return;
    int u = edges[2 * e];
    float mo = fkey_inv(g_mkey_o[u]);
    float mn = fkey_inv(g_mkey_n[u]);
    atomicAdd(&g_ssum_o[u], expf(g_sims_o[e] - mo));
    atomicAdd(&g_ssum_n[u], expf(g_sims_n[e] - mn));
    atomicAdd(&g_cnt[u], 1.f);
}

__device__ __forceinline__ void hscale_block(int blk, const float4* __restrict__ H4) {
    int i = blk * 256 + threadIdx.x;
    if (i >= NA * DEMB / 4) return;
    int j = i >> 5;
    float dv = g_dinv[j];
    float4 h = H4[i];
    __nv_bfloat162 p0 = __floats2bfloat162_rn(h.x * dv, h.y * dv);
    __nv_bfloat162 p1 = __floats2bfloat162_rn(h.z * dv, h.w * dv);
    uint2 o;
    o.x = *(unsigned*)&p0;
    o.y = *(unsigned*)&p1;
    ((uint2*)g_Hs)[i] = o;
}

__global__ __launch_bounds__(256)
void mega2_kernel(const int* __restrict__ rE, int nR, const float4* __restrict__ H4) {
    int b = blockIdx.x;
    if (b < 32) segsum_block(b, rE, nR);
    else        hscale_block(b - 32, H4);
}

// ---------------- K4: gemm (blocks 0..127) + lp (blocks 128..159) -----------
#define MBLK   64
#define KBLK   64
#define STAGES 4
#define NCHUNK (NA / KBLK)              // 128
#define ATILE  8192                     // 64 rows * 64 k * 2B
#define BTILE  16384                    // 64 k * 128 n * 2B
#define STAGEB (ATILE + BTILE)          // 24576
#define GEMM_SMEM (STAGES * STAGEB)     // 98304

__device__ __forceinline__ void lp_block(int blk, const int* __restrict__ edges, int nE) {
    int e = blk * 256 + threadIdx.x;
    if (e >= nE) return;
    int u = edges[2 * e];
    if (g_cnt[u] <= 1.f) return;
    float mo = fkey_inv(g_mkey_o[u]);
    float lseo = logf(g_ssum_o[u] + 1e-30f) + mo;
    float lpo  = logf(expf(g_sims_o[e] - lseo) + FEPS);
    float mn = fkey_inv(g_mkey_n[u]);
    float lsen = logf(g_ssum_n[u] + 1e-30f) + mn;
    float lpn  = logf(expf(g_sims_n[e] - lsen) + FEPS);
    float d = lpn - lpo;
    atomicAdd(&g_LpNum, d * d);
    atomicAdd(&g_LpDen, 1.f);
}

__device__ void gemm_block(const float* __restrict__ H, char* smem) {
    __shared__ float s_num[MBLK], s_sq[MBLK];
    uint32_t sb = s2u(smem);
    const int tid = threadIdx.x;
    const int lane = tid & 31;
    const int wid = tid >> 5;
    const int wm = wid & 1;              // 0..1 (M)
    const int wn = wid >> 1;             // 0..3 (N)
    const int bi = blockIdx.x * MBLK;

    if (tid < MBLK) { s_num[tid] = 0.f; s_sq[tid] = 0.f; }

    const unsigned short* __restrict__ W = g_Wbf;
    const unsigned short* __restrict__ Hs = g_Hs;

    // A: 64 rows x 8 chunks(16B) = 512 cp16 -> 2 per thread
    // B: 64 k x 16 chunks(16B) = 1024 cp16 -> 4 per thread
    auto issue_loads = [&](int n) {
        uint32_t st = sb + (n % STAGES) * STAGEB;
        long long j0 = (long long)n * KBLK;
#pragma unroll
        for (int q = 0; q < 2; q++) {
            int id = tid + q * 256;
            int r = id >> 3, c = id & 7;
            uint32_t off = (uint32_t)(r * 128 + ((c ^ (r & 7)) << 4));
            cp16(st + off, W + (long long)(bi + r) * NA + j0 + c * 8);
        }
#pragma unroll
        for (int q = 0; q < 4; q++) {
            int id = tid + q * 256;
            int k = id >> 4, c = id & 15;
            uint32_t off = (uint32_t)(k * 256 + ((c ^ (k & 7)) << 4));
            cp16(st + ATILE + off, Hs + (j0 + k) * DEMB + c * 8);
        }
        CP_COMMIT();
    };

    float acc[2][4][4];
#pragma unroll
    for (int mt = 0; mt < 2; mt++)
#pragma unroll
        for (int nt = 0; nt < 4; nt++)
#pragma unroll
            for (int q = 0; q < 4; q++) acc[mt][nt][q] = 0.f;

    const int grp = lane >> 3;                 // 0..3
    const int l7  = lane & 7;
    const int ar_base = wm * 32 + l7 + ((grp & 1) << 3);
    const int ac_add  = grp >> 1;
    const int bk_base = l7 + ((grp & 1) << 3);
    const int bc_add  = grp >> 1;

    issue_loads(0); issue_loads(1); issue_loads(2);

    for (int c = 0; c < NCHUNK; c++) {
        CP_WAIT2();
        __syncthreads();
        uint32_t Ab = sb + (c % STAGES) * STAGEB;
        uint32_t Bb = Ab + ATILE;

#pragma unroll
        for (int kk = 0; kk < 4; kk++) {       // four k16 steps
            uint32_t af[2][4];
#pragma unroll
            for (int mt = 0; mt < 2; mt++) {
                int r = ar_base + mt * 16;
                int ch = kk * 2 + ac_add;
                ldsm4(af[mt], Ab + (uint32_t)(r * 128 + ((ch ^ (r & 7)) << 4)));
            }
            uint32_t bf[4][2];
#pragma unroll
            for (int cp = 0; cp < 2; cp++) {
                int k = kk * 16 + bk_base;
                int cn = wn * 4 + cp * 2 + bc_add;
                uint32_t t4[4];
                ldsm4t(t4, Bb + (uint32_t)(k * 256 + ((cn ^ (k & 7)) << 4)));
                bf[cp * 2 + 0][0] = t4[0]; bf[cp * 2 + 0][1] = t4[1];
                bf[cp * 2 + 1][0] = t4[2]; bf[cp * 2 + 1][1] = t4[3];
            }
#pragma unroll
            for (int mt = 0; mt < 2; mt++)
#pragma unroll
                for (int nt = 0; nt < 4; nt++)
                    mma16816(acc[mt][nt], af[mt], bf[nt]);
        }

        int n = c + 3;
        if (n < NCHUNK) issue_loads(n);
        else            CP_COMMIT();
    }

    // ---- epilogue: per-row num = <H, Hp>, sq = |Hp|^2 ----
    __syncthreads();
#pragma unroll
    for (int mt = 0; mt < 2; mt++) {
#pragma unroll
        for (int half = 0; half < 2; half++) {
            int rl = wm * 32 + mt * 16 + half * 8 + (lane >> 2);
            long long gi = bi + rl;
            float num = 0.f, sq = 0.f;
#pragma unroll
            for (int nt = 0; nt < 4; nt++) {
                int col = wn * 32 + nt * 8 + (lane & 3) * 2;
                float v0 = acc[mt][nt][half * 2 + 0];
                float v1 = acc[mt][nt][half * 2 + 1];
                float h0 = H[gi * DEMB + col];
                float h1 = H[gi * DEMB + col + 1];
                num += h0 * v0 + h1 * v1;
                sq  += v0 * v0 + v1 * v1;
            }
            num += __shfl_xor_sync(~0u, num, 1);
            num += __shfl_xor_sync(~0u, num, 2);
            sq  += __shfl_xor_sync(~0u, sq, 1);
            sq  += __shfl_xor_sync(~0u, sq, 2);
            if ((lane & 3) == 0) {
                atomicAdd(&s_num[rl], num);
                atomicAdd(&s_sq[rl], sq);
            }
        }
    }
    __syncthreads();

    if (tid < MBLK) {
        long long gi = bi + tid;
        const float4* hb = (const float4*)(H + gi * DEMB);
        float hsq = 0.f;
#pragma unroll
        for (int q = 0; q < 32; q++) {
            float4 h = hb[q];
            hsq += h.x * h.x + h.y * h.y + h.z * h.z + h.w * h.w;
        }
        float dv  = g_dinv[gi];
        float den = fmaxf(sqrtf(hsq) * (dv * sqrtf(s_sq[tid])), FEPS);
        float cosv = dv * s_num[tid] / den;
        float val = softplusf(-cosv);
#pragma unroll
        for (int o = 16; o; o >>= 1) val += __shfl_xor_sync(~0u, val, o);
        if ((tid & 31) == 0) atomicAdd(&g_Lc, val);
    }
}

__global__ __launch_bounds__(256, 1)
void mega3_kernel(const float* __restrict__ H, const int* __restrict__ rE, int nR) {
    extern __shared__ char smem[];
    if (blockIdx.x < 128) gemm_block(H, smem);
    else                  lp_block(blockIdx.x - 128, rE, nR);
}

// ---------------- finalize --------------------------------------------------
__global__ void final_kernel(float* __restrict__ out, int nU) {
    float L_u = g_Lu / (float)nU;
    float L_p = g_LpNum / fmaxf(g_LpDen, 1.f);
    float L_c = g_Lc / (float)NA;
    out[0] = L_u + L_p + 0.01f * L_c;
    out[1] = L_u;
    out[2] = L_p;
    out[3] = L_c;
}

// ---------------- launch ----------------------------------------------------
extern "C" void kernel_launch(void* const* d_in, const int* in_sizes, int n_in,
                              void* d_out, int out_size) {
    const float* pred = (const float*)d_in[0];
    const float* embO = (const float*)d_in[1];
    const float* embN = (const float*)d_in[2];
    const float* A    = (const float*)d_in[3];
    const float* H    = (const float*)d_in[4];
    const int*   uE   = (const int*)d_in[5];
    const int*   rE   = (const int*)d_in[6];
    const void*  mask = d_in[7];
    int nU = in_sizes[5] / 2;
    int nR = in_sizes[6] / 2;

    cudaFuncSetAttribute(mega3_kernel,
                         cudaFuncAttributeMaxDynamicSharedMemorySize, GEMM_SMEM);

    init_kernel<<<(NEMB + 255) / 256, 256>>>((const unsigned*)mask);
    mega1_kernel<<<NA + 16 + 1024, 256>>>((const float4*)A, mask, pred,
                                          embO, embN, uE, nU, rE, nR);
    mega2_kernel<<<32 + 1024, 256>>>(rE, nR, (const float4*)H);
    mega3_kernel<<<128 + 32, 256, GEMM_SMEM>>>(H, rE, nR);
    final_kernel<<<1, 1>>>((float*)d_out, nU);
}